// round 1
// baseline (speedup 1.0000x reference)
#include <cuda_runtime.h>
#include <math.h>

#define Tn 1024
#define Hn 1024
#define En 64
#define In 512
#define TWO_I 1024
#define Gn 8
#define EPG 8
#define TOPKG 4
#define TOPK 8
#define NV 65                 // 64 routed + 1 shared (virtual expert 64)

#define BM 64
#define BN 64
#define BK 16

// ---------------- device scratch (no runtime allocation allowed) ----------------
__device__ int   g_counts[NV];
__device__ int   g_offsets[NV];
__device__ int   g_tokens[NV * Tn];
__device__ int   g_tk_e[Tn * TOPK];
__device__ int   g_tk_pos[Tn * TOPK];
__device__ float g_tk_w[Tn * TOPK];
__device__ float g_act[(size_t)(Tn * TOPK + Tn) * In];   // 18.9 MB
__device__ float g_down[(size_t)(Tn * TOPK + Tn) * Hn];  // 37.7 MB

// ---------------- helpers ----------------
__device__ __forceinline__ unsigned f2tf(float f) {
    unsigned u;
    asm("cvt.rna.tf32.f32 %0, %1;" : "=r"(u) : "f"(f));
    return u;
}

__device__ __forceinline__ void mma_tf32(float* d, unsigned a0, unsigned a1,
                                         unsigned a2, unsigned a3,
                                         unsigned b0, unsigned b1) {
    asm volatile(
        "mma.sync.aligned.m16n8k8.row.col.f32.tf32.tf32.f32 "
        "{%0,%1,%2,%3}, {%4,%5,%6,%7}, {%8,%9}, {%0,%1,%2,%3};"
        : "+f"(d[0]), "+f"(d[1]), "+f"(d[2]), "+f"(d[3])
        : "r"(a0), "r"(a1), "r"(a2), "r"(a3), "r"(b0), "r"(b1));
}

// ---------------- kernel 0: init ----------------
__global__ void k_init() {
    int tid = threadIdx.x;
    if (tid < En) g_counts[tid] = 0;
    if (tid == En) g_counts[En] = Tn;  // shared expert processes all tokens
}

// ---------------- kernel 1: routing ----------------
// 1 block per token, 256 threads. logits in exact fp32, grouped top-k matching
// lax.top_k tie semantics (strict '>' => lowest index wins on ties).
__global__ void k_route(const float* __restrict__ x,
                        const float* __restrict__ gw,
                        const float* __restrict__ ebias) {
    int t = blockIdx.x;
    int tid = threadIdx.x;
    __shared__ float s_x[Hn];
    __shared__ float s_sc[En];
    __shared__ float s_ch[En];

    for (int i = tid; i < Hn / 4; i += 256)
        ((float4*)s_x)[i] = ((const float4*)(x + (size_t)t * Hn))[i];
    __syncthreads();

    int e = tid >> 2, p = tid & 3;  // 4 threads per expert
    const float* gr = gw + (size_t)e * Hn;
    float part = 0.f;
    #pragma unroll 8
    for (int j = 0; j < Hn / 4; j++) {
        int h = j * 4 + p;
        part += s_x[h] * gr[h];
    }
    part += __shfl_xor_sync(0xffffffffu, part, 1);
    part += __shfl_xor_sync(0xffffffffu, part, 2);
    if (p == 0) {
        float sc = 1.f / (1.f + expf(-part));
        s_sc[e] = sc;
        s_ch[e] = sc + ebias[e];
    }
    if (tid == 0) g_tokens[En * Tn + t] = t;  // shared expert token list
    __syncthreads();

    if (tid == 0) {
        // group scores = sum of top-2 s_choice per group
        float gs[Gn];
        #pragma unroll
        for (int g = 0; g < Gn; g++) {
            float m1 = -1e38f, m2 = -1e38f;
            #pragma unroll
            for (int j = 0; j < EPG; j++) {
                float v = s_ch[g * EPG + j];
                if (v > m1) { m2 = m1; m1 = v; }
                else if (v > m2) { m2 = v; }
            }
            gs[g] = m1 + m2;
        }
        // top-4 groups
        unsigned gsel = 0;
        #pragma unroll
        for (int it = 0; it < TOPKG; it++) {
            float best = -1e38f; int bi = 0;
            #pragma unroll
            for (int g = 0; g < Gn; g++)
                if (!((gsel >> g) & 1u) && gs[g] > best) { best = gs[g]; bi = g; }
            gsel |= 1u << bi;
        }
        // top-8 experts among allowed groups (by s_choice), weight = raw score
        unsigned long long taken = 0ull;
        int eidx[TOPK]; float ws[TOPK]; float wsum = 0.f;
        #pragma unroll
        for (int it = 0; it < TOPK; it++) {
            float best = -1e38f; int bi = 0;
            for (int ee = 0; ee < En; ee++) {
                if (((gsel >> (ee >> 3)) & 1u) && !((taken >> ee) & 1ull)) {
                    float v = s_ch[ee];
                    if (v > best) { best = v; bi = ee; }
                }
            }
            taken |= 1ull << bi;
            eidx[it] = bi; ws[it] = s_sc[bi]; wsum += s_sc[bi];
        }
        float scale = 1.0f / wsum;  // RSF = 1
        #pragma unroll
        for (int k = 0; k < TOPK; k++) {
            int ee = eidx[k];
            int pos = atomicAdd(&g_counts[ee], 1);
            g_tokens[ee * Tn + pos] = t;
            g_tk_e[t * TOPK + k]   = ee;
            g_tk_pos[t * TOPK + k] = pos;
            g_tk_w[t * TOPK + k]   = ws[k] * scale;
        }
    }
}

// ---------------- kernel 2: offsets (exclusive scan over 65 counts) ----------------
__global__ void k_scan() {
    int off = 0;
    for (int e = 0; e < NV; e++) { g_offsets[e] = off; off += g_counts[e]; }
}

// ---------------- kernel 3: gate_up GEMM + SiLU*up ----------------
// Per virtual expert e: act[m,i] = silu(X_e @ Wg[:,i]) * (X_e @ Wg[:,I+i])
// Block tile 64(M) x 64(gate N, + matching up N), BK=16, 4 warps each 16x64.
__global__ __launch_bounds__(128) void k_gemm1(const float* __restrict__ x,
                                               const float* __restrict__ wgu,
                                               const float* __restrict__ shgu) {
    const int e = blockIdx.y;
    const int n_e = g_counts[e];
    const int nt = blockIdx.x & 7;   // 8 N tiles over I=512
    const int mt = blockIdx.x >> 3;  // 16 M tiles over up to 1024 rows
    const int row0 = mt * BM;
    if (row0 >= n_e) return;
    const float* B = (e < En) ? (wgu + (size_t)e * Hn * TWO_I) : shgu;
    const int off_e = g_offsets[e];

    __shared__ float As[BM][20];
    __shared__ float Bg[BK][72];
    __shared__ float Bu[BK][72];
    __shared__ int s_tok[BM];

    const int tid = threadIdx.x;
    if (tid < BM) {
        int r = row0 + tid;
        s_tok[tid] = (r < n_e) ? g_tokens[e * Tn + r] : -1;
    }
    __syncthreads();

    const int w = tid >> 5, lane = tid & 31;
    const int wrow = w * 16;
    const int qr = lane >> 2, qc = lane & 3;

    float accG[8][4], accU[8][4];
    #pragma unroll
    for (int i = 0; i < 8; i++)
        #pragma unroll
        for (int j = 0; j < 4; j++) { accG[i][j] = 0.f; accU[i][j] = 0.f; }

    const int colg = nt * BN;
    for (int kk = 0; kk < Hn; kk += BK) {
        #pragma unroll
        for (int l = 0; l < 2; l++) {  // A: 64 rows x 4 float4
            int idx = tid + l * 128;
            int ar = idx & 63, ac4 = idx >> 6;
            int tok = s_tok[ar];
            float4 v = make_float4(0.f, 0.f, 0.f, 0.f);
            if (tok >= 0) v = *(const float4*)(x + (size_t)tok * Hn + kk + ac4 * 4);
            *(float4*)(&As[ar][ac4 * 4]) = v;
        }
        #pragma unroll
        for (int l = 0; l < 2; l++) {  // B: 16 rows x 16 float4 (gate + up)
            int idx = tid + l * 128;
            int br = idx >> 4, bc4 = idx & 15;
            const float* bp = B + (size_t)(kk + br) * TWO_I + colg + bc4 * 4;
            *(float4*)(&Bg[br][bc4 * 4]) = *(const float4*)(bp);
            *(float4*)(&Bu[br][bc4 * 4]) = *(const float4*)(bp + In);
        }
        __syncthreads();
        #pragma unroll
        for (int ks = 0; ks < BK; ks += 8) {
            unsigned a0 = f2tf(As[wrow + qr][ks + qc]);
            unsigned a1 = f2tf(As[wrow + qr + 8][ks + qc]);
            unsigned a2 = f2tf(As[wrow + qr][ks + qc + 4]);
            unsigned a3 = f2tf(As[wrow + qr + 8][ks + qc + 4]);
            #pragma unroll
            for (int ntile = 0; ntile < 8; ntile++) {
                int bc = ntile * 8 + qr;
                unsigned bg0 = f2tf(Bg[ks + qc][bc]);
                unsigned bg1 = f2tf(Bg[ks + qc + 4][bc]);
                mma_tf32(accG[ntile], a0, a1, a2, a3, bg0, bg1);
                unsigned bu0 = f2tf(Bu[ks + qc][bc]);
                unsigned bu1 = f2tf(Bu[ks + qc + 4][bc]);
                mma_tf32(accU[ntile], a0, a1, a2, a3, bu0, bu1);
            }
        }
        __syncthreads();
    }
    // epilogue: silu(g)*u
    #pragma unroll
    for (int ntile = 0; ntile < 8; ntile++) {
        #pragma unroll
        for (int half = 0; half < 2; half++) {
            int r = wrow + qr + half * 8;
            int grow = row0 + r;
            if (grow < n_e) {
                int c = ntile * 8 + qc * 2;
                float gv0 = accG[ntile][half * 2 + 0], uv0 = accU[ntile][half * 2 + 0];
                float gv1 = accG[ntile][half * 2 + 1], uv1 = accU[ntile][half * 2 + 1];
                float o0 = gv0 / (1.f + expf(-gv0)) * uv0;
                float o1 = gv1 / (1.f + expf(-gv1)) * uv1;
                float* dst = g_act + (size_t)(off_e + grow) * In + colg + c;
                dst[0] = o0; dst[1] = o1;
            }
        }
    }
}

// ---------------- kernel 4: down GEMM ----------------
// g_down[slot, h] = act[slot,:] @ Wd[:,h]  (weights applied later in combine)
__global__ __launch_bounds__(128) void k_gemm2(const float* __restrict__ wd,
                                               const float* __restrict__ shd) {
    const int e = blockIdx.y;
    const int n_e = g_counts[e];
    const int nt = blockIdx.x & 15;  // 16 N tiles over H=1024
    const int mt = blockIdx.x >> 4;
    const int row0 = mt * BM;
    if (row0 >= n_e) return;
    const float* B = (e < En) ? (wd + (size_t)e * In * Hn) : shd;
    const int off_e = g_offsets[e];

    __shared__ float As[BM][20];
    __shared__ float Bs[BK][72];

    const int tid = threadIdx.x;
    const int w = tid >> 5, lane = tid & 31;
    const int wrow = w * 16;
    const int qr = lane >> 2, qc = lane & 3;

    float acc[8][4];
    #pragma unroll
    for (int i = 0; i < 8; i++)
        #pragma unroll
        for (int j = 0; j < 4; j++) acc[i][j] = 0.f;

    const int colb = nt * BN;
    for (int kk = 0; kk < In; kk += BK) {
        #pragma unroll
        for (int l = 0; l < 2; l++) {
            int idx = tid + l * 128;
            int ar = idx & 63, ac4 = idx >> 6;
            int grow = row0 + ar;
            float4 v = make_float4(0.f, 0.f, 0.f, 0.f);
            if (grow < n_e)
                v = *(const float4*)(g_act + (size_t)(off_e + grow) * In + kk + ac4 * 4);
            *(float4*)(&As[ar][ac4 * 4]) = v;
        }
        #pragma unroll
        for (int l = 0; l < 2; l++) {
            int idx = tid + l * 128;
            int br = idx >> 4, bc4 = idx & 15;
            *(float4*)(&Bs[br][bc4 * 4]) =
                *(const float4*)(B + (size_t)(kk + br) * Hn + colb + bc4 * 4);
        }
        __syncthreads();
        #pragma unroll
        for (int ks = 0; ks < BK; ks += 8) {
            unsigned a0 = f2tf(As[wrow + qr][ks + qc]);
            unsigned a1 = f2tf(As[wrow + qr + 8][ks + qc]);
            unsigned a2 = f2tf(As[wrow + qr][ks + qc + 4]);
            unsigned a3 = f2tf(As[wrow + qr + 8][ks + qc + 4]);
            #pragma unroll
            for (int ntile = 0; ntile < 8; ntile++) {
                int bc = ntile * 8 + qr;
                unsigned b0 = f2tf(Bs[ks + qc][bc]);
                unsigned b1 = f2tf(Bs[ks + qc + 4][bc]);
                mma_tf32(acc[ntile], a0, a1, a2, a3, b0, b1);
            }
        }
        __syncthreads();
    }
    #pragma unroll
    for (int ntile = 0; ntile < 8; ntile++) {
        #pragma unroll
        for (int half = 0; half < 2; half++) {
            int r = wrow + qr + half * 8;
            int grow = row0 + r;
            if (grow < n_e) {
                int c = colb + ntile * 8 + qc * 2;
                float* dst = g_down + (size_t)(off_e + grow) * Hn + c;
                dst[0] = acc[ntile][half * 2 + 0];
                dst[1] = acc[ntile][half * 2 + 1];
            }
        }
    }
}

// ---------------- kernel 5: weighted combine (deterministic, no atomics) --------
__global__ void k_combine(float* __restrict__ out) {
    int t = blockIdx.x, tid = threadIdx.x;
    __shared__ int s_slot[9];
    __shared__ float s_w[9];
    if (tid < TOPK) {
        int ee = g_tk_e[t * TOPK + tid];
        s_slot[tid] = g_offsets[ee] + g_tk_pos[t * TOPK + tid];
        s_w[tid] = g_tk_w[t * TOPK + tid];
    } else if (tid == TOPK) {
        s_slot[8] = g_offsets[En] + t;  // shared expert slot
        s_w[8] = 1.f;
    }
    __syncthreads();
    int h = tid * 4;
    float4 acc = make_float4(0.f, 0.f, 0.f, 0.f);
    #pragma unroll
    for (int j = 0; j < 9; j++) {
        float4 v = *(const float4*)(g_down + (size_t)s_slot[j] * Hn + h);
        float wv = s_w[j];
        acc.x += wv * v.x; acc.y += wv * v.y;
        acc.z += wv * v.z; acc.w += wv * v.w;
    }
    *(float4*)(out + (size_t)t * Hn + h) = acc;
}

// ---------------- launch ----------------
extern "C" void kernel_launch(void* const* d_in, const int* in_sizes, int n_in,
                              void* d_out, int out_size) {
    const float* x    = (const float*)d_in[0];  // hidden_states [T,H]
    const float* gw   = (const float*)d_in[1];  // gate_w [E,H]
    const float* eb   = (const float*)d_in[2];  // e_bias [E]
    const float* wgu  = (const float*)d_in[3];  // w_gate_up [E,H,2I]
    const float* wd   = (const float*)d_in[4];  // w_down [E,I,H]
    const float* shgu = (const float*)d_in[5];  // sh_gate_up [H,2I]
    const float* shd  = (const float*)d_in[6];  // sh_down [I,H]
    float* out = (float*)d_out;

    k_init<<<1, 128>>>();
    k_route<<<Tn, 256>>>(x, gw, eb);
    k_scan<<<1, 1>>>();
    k_gemm1<<<dim3(16 * 8, NV), 128>>>(x, wgu, shgu);
    k_gemm2<<<dim3(16 * 16, NV), 128>>>(wd, shd);
    k_combine<<<Tn, 256>>>(out);
}

// round 3
// speedup vs baseline: 1.6819x; 1.6819x over previous
#include <cuda_runtime.h>
#include <math.h>

#define Tn 1024
#define Hn 1024
#define En 64
#define In 512
#define TWO_I 1024
#define Gn 8
#define EPG 8
#define TOPKG 4
#define TOPK 8
#define NV 65                 // 64 routed + 1 shared (virtual expert 64)

#define BM 64
#define BN 64
#define BK 32

// ---------------- device scratch (no runtime allocation allowed) ----------------
__device__ int   g_counts[NV];
__device__ int   g_offsets[NV];
__device__ int   g_tokens[NV * Tn];
__device__ int   g_tk_e[Tn * TOPK];
__device__ int   g_tk_pos[Tn * TOPK];
__device__ float g_tk_w[Tn * TOPK];
__device__ float g_act[(size_t)(Tn * TOPK + Tn) * In];   // 18.9 MB
__device__ float g_down[(size_t)(Tn * TOPK + Tn) * Hn];  // 37.7 MB

// ---------------- helpers ----------------
__device__ __forceinline__ unsigned f2tf(float f) {
    unsigned u;
    asm("cvt.rna.tf32.f32 %0, %1;" : "=r"(u) : "f"(f));
    return u;
}

__device__ __forceinline__ void mma_tf32(float* d, unsigned a0, unsigned a1,
                                         unsigned a2, unsigned a3,
                                         unsigned b0, unsigned b1) {
    asm volatile(
        "mma.sync.aligned.m16n8k8.row.col.f32.tf32.tf32.f32 "
        "{%0,%1,%2,%3}, {%4,%5,%6,%7}, {%8,%9}, {%0,%1,%2,%3};"
        : "+f"(d[0]), "+f"(d[1]), "+f"(d[2]), "+f"(d[3])
        : "r"(a0), "r"(a1), "r"(a2), "r"(a3), "r"(b0), "r"(b1));
}

__device__ __forceinline__ void cpa16(void* dst, const void* src) {
    unsigned d = (unsigned)__cvta_generic_to_shared(dst);
    asm volatile("cp.async.cg.shared.global [%0], [%1], 16;" :: "r"(d), "l"(src));
}
__device__ __forceinline__ void cpa_commit() {
    asm volatile("cp.async.commit_group;");
}
__device__ __forceinline__ void cpa_wait1() {
    asm volatile("cp.async.wait_group 1;");
}
__device__ __forceinline__ void cpa_wait0() {
    asm volatile("cp.async.wait_group 0;");
}

// SMEM strides (floats). AS_P%32==4 -> A frag loads conflict-free,
// BS_P%32==8 -> B frag loads conflict-free. Both 16B-aligned for cp.async.
#define AS_P 36
#define BS_P 72

// ---------------- kernel 0: init ----------------
__global__ void k_init() {
    int tid = threadIdx.x;
    if (tid < En) g_counts[tid] = 0;
    if (tid == En) g_counts[En] = Tn;  // shared expert processes all tokens
}

// ---------------- kernel 1: routing ----------------
__global__ void k_route(const float* __restrict__ x,
                        const float* __restrict__ gw,
                        const float* __restrict__ ebias) {
    int t = blockIdx.x;
    int tid = threadIdx.x;
    __shared__ float s_x[Hn];
    __shared__ float s_sc[En];
    __shared__ float s_ch[En];

    for (int i = tid; i < Hn / 4; i += 256)
        ((float4*)s_x)[i] = ((const float4*)(x + (size_t)t * Hn))[i];
    __syncthreads();

    int e = tid >> 2, p = tid & 3;  // 4 threads per expert
    const float* gr = gw + (size_t)e * Hn;
    float part = 0.f;
    #pragma unroll 8
    for (int j = 0; j < Hn / 4; j++) {
        int h = j * 4 + p;
        part += s_x[h] * gr[h];
    }
    part += __shfl_xor_sync(0xffffffffu, part, 1);
    part += __shfl_xor_sync(0xffffffffu, part, 2);
    if (p == 0) {
        float sc = 1.f / (1.f + expf(-part));
        s_sc[e] = sc;
        s_ch[e] = sc + ebias[e];
    }
    if (tid == 0) g_tokens[En * Tn + t] = t;  // shared expert token list
    __syncthreads();

    if (tid == 0) {
        float gs[Gn];
        #pragma unroll
        for (int g = 0; g < Gn; g++) {
            float m1 = -1e38f, m2 = -1e38f;
            #pragma unroll
            for (int j = 0; j < EPG; j++) {
                float v = s_ch[g * EPG + j];
                if (v > m1) { m2 = m1; m1 = v; }
                else if (v > m2) { m2 = v; }
            }
            gs[g] = m1 + m2;
        }
        unsigned gsel = 0;
        #pragma unroll
        for (int it = 0; it < TOPKG; it++) {
            float best = -1e38f; int bi = 0;
            #pragma unroll
            for (int g = 0; g < Gn; g++)
                if (!((gsel >> g) & 1u) && gs[g] > best) { best = gs[g]; bi = g; }
            gsel |= 1u << bi;
        }
        unsigned long long taken = 0ull;
        int eidx[TOPK]; float ws[TOPK]; float wsum = 0.f;
        #pragma unroll
        for (int it = 0; it < TOPK; it++) {
            float best = -1e38f; int bi = 0;
            for (int ee = 0; ee < En; ee++) {
                if (((gsel >> (ee >> 3)) & 1u) && !((taken >> ee) & 1ull)) {
                    float v = s_ch[ee];
                    if (v > best) { best = v; bi = ee; }
                }
            }
            taken |= 1ull << bi;
            eidx[it] = bi; ws[it] = s_sc[bi]; wsum += s_sc[bi];
        }
        float scale = 1.0f / wsum;  // RSF = 1
        #pragma unroll
        for (int k = 0; k < TOPK; k++) {
            int ee = eidx[k];
            int pos = atomicAdd(&g_counts[ee], 1);
            g_tokens[ee * Tn + pos] = t;
            g_tk_e[t * TOPK + k]   = ee;
            g_tk_pos[t * TOPK + k] = pos;
            g_tk_w[t * TOPK + k]   = ws[k] * scale;
        }
    }
}

// ---------------- kernel 2: offsets ----------------
__global__ void k_scan() {
    int off = 0;
    for (int e = 0; e < NV; e++) { g_offsets[e] = off; off += g_counts[e]; }
}

// ---------------- kernel 3: gate_up GEMM + SiLU*up ----------------
// Block 64M x (64 gate + 64 up), BK=32 double-buffered cp.async.
// 4 warps in 2x2; warp tile 32M x 32N (for both G and U).
__global__ __launch_bounds__(128, 3) void k_gemm1(const float* __restrict__ x,
                                                  const float* __restrict__ wgu,
                                                  const float* __restrict__ shgu) {
    const int e = blockIdx.y;
    const int n_e = g_counts[e];
    const int nt = blockIdx.x & 7;   // 8 N tiles over I=512
    const int mt = blockIdx.x >> 3;  // 16 M tiles
    const int row0 = mt * BM;
    if (row0 >= n_e) return;
    const float* B = (e < En) ? (wgu + (size_t)e * Hn * TWO_I) : shgu;
    const int off_e = g_offsets[e];
    const int colg = nt * BN;

    extern __shared__ float smem[];
    float* As = smem;                       // [2][64][AS_P]
    float* Bg = smem + 2 * BM * AS_P;       // [2][32][BS_P]
    float* Bu = Bg + 2 * BK * BS_P;         // [2][32][BS_P]

    const int tid = threadIdx.x;

    // --- per-thread cp.async source pointers ---
    const float* a_src[4];
    float* a_dst[4];
    {
        int c4 = tid & 7;
        #pragma unroll
        for (int l = 0; l < 4; l++) {
            int r = (tid >> 3) + 16 * l;
            int ridx = row0 + r; if (ridx > n_e - 1) ridx = n_e - 1;
            int tok = g_tokens[e * Tn + ridx];
            a_src[l] = x + (size_t)tok * Hn + c4 * 4;
            a_dst[l] = As + r * AS_P + c4 * 4;
        }
    }
    const float* b_src[8];
    float* b_dst[8];
    {
        int c4 = tid & 15;
        #pragma unroll
        for (int l = 0; l < 8; l++) {
            int id = tid + l * 128;
            int m = id >> 9;
            int r = (id >> 4) & 31;
            b_src[l] = B + (size_t)r * TWO_I + colg + m * In + c4 * 4;
            b_dst[l] = (m ? Bu : Bg) + r * BS_P + c4 * 4;
        }
    }

    const int w = tid >> 5, lane = tid & 31;
    const int wm = w & 1, wn = w >> 1;
    const int qr = lane >> 2, qc = lane & 3;
    const int abuf_sz = BM * AS_P, bbuf_sz = BK * BS_P;

    float accG[2][4][4], accU[2][4][4];
    #pragma unroll
    for (int m = 0; m < 2; m++)
        #pragma unroll
        for (int n = 0; n < 4; n++)
            #pragma unroll
            for (int j = 0; j < 4; j++) { accG[m][n][j] = 0.f; accU[m][n][j] = 0.f; }

    // prologue: stage 0
    #pragma unroll
    for (int l = 0; l < 4; l++) cpa16(a_dst[l], a_src[l]);
    #pragma unroll
    for (int l = 0; l < 8; l++) cpa16(b_dst[l], b_src[l]);
    cpa_commit();

    const int KT = Hn / BK;  // 32
    for (int kt = 0; kt < KT; kt++) {
        int buf = kt & 1;
        if (kt + 1 < KT) {
            int nb = buf ^ 1;
            int aoff = nb ? abuf_sz : 0;
            int boff = nb ? bbuf_sz : 0;
            size_t ka = (size_t)(kt + 1) * BK;
            #pragma unroll
            for (int l = 0; l < 4; l++)
                cpa16(a_dst[l] + aoff, a_src[l] + ka);
            #pragma unroll
            for (int l = 0; l < 8; l++)
                cpa16(b_dst[l] + boff, b_src[l] + ka * TWO_I);
            cpa_commit();
            cpa_wait1();
        } else {
            cpa_wait0();
        }
        __syncthreads();

        const float* Ab = As + buf * abuf_sz;
        const float* Bgb = Bg + buf * bbuf_sz;
        const float* Bub = Bu + buf * bbuf_sz;
        #pragma unroll
        for (int ks = 0; ks < BK; ks += 8) {
            unsigned a[2][4];
            #pragma unroll
            for (int m = 0; m < 2; m++) {
                int r0 = wm * 32 + m * 16 + qr;
                a[m][0] = f2tf(Ab[r0 * AS_P + ks + qc]);
                a[m][1] = f2tf(Ab[(r0 + 8) * AS_P + ks + qc]);
                a[m][2] = f2tf(Ab[r0 * AS_P + ks + qc + 4]);
                a[m][3] = f2tf(Ab[(r0 + 8) * AS_P + ks + qc + 4]);
            }
            #pragma unroll
            for (int n = 0; n < 4; n++) {
                int c = wn * 32 + n * 8 + qr;
                unsigned bg0 = f2tf(Bgb[(ks + qc) * BS_P + c]);
                unsigned bg1 = f2tf(Bgb[(ks + qc + 4) * BS_P + c]);
                #pragma unroll
                for (int m = 0; m < 2; m++)
                    mma_tf32(accG[m][n], a[m][0], a[m][1], a[m][2], a[m][3], bg0, bg1);
                unsigned bu0 = f2tf(Bub[(ks + qc) * BS_P + c]);
                unsigned bu1 = f2tf(Bub[(ks + qc + 4) * BS_P + c]);
                #pragma unroll
                for (int m = 0; m < 2; m++)
                    mma_tf32(accU[m][n], a[m][0], a[m][1], a[m][2], a[m][3], bu0, bu1);
            }
        }
        __syncthreads();
    }

    // epilogue: silu(g)*u
    #pragma unroll
    for (int m = 0; m < 2; m++) {
        #pragma unroll
        for (int n = 0; n < 4; n++) {
            #pragma unroll
            for (int half = 0; half < 2; half++) {
                int r = wm * 32 + m * 16 + qr + half * 8;
                int grow = row0 + r;
                if (grow < n_e) {
                    int c = colg + wn * 32 + n * 8 + qc * 2;
                    float gv0 = accG[m][n][half * 2 + 0], uv0 = accU[m][n][half * 2 + 0];
                    float gv1 = accG[m][n][half * 2 + 1], uv1 = accU[m][n][half * 2 + 1];
                    float2 o;
                    o.x = gv0 / (1.f + expf(-gv0)) * uv0;
                    o.y = gv1 / (1.f + expf(-gv1)) * uv1;
                    *(float2*)(g_act + (size_t)(off_e + grow) * In + c) = o;
                }
            }
        }
    }
}

// ---------------- kernel 4: down GEMM ----------------
__global__ __launch_bounds__(128, 4) void k_gemm2(const float* __restrict__ wd,
                                                  const float* __restrict__ shd) {
    const int e = blockIdx.y;
    const int n_e = g_counts[e];
    const int nt = blockIdx.x & 15;  // 16 N tiles over H=1024
    const int mt = blockIdx.x >> 4;
    const int row0 = mt * BM;
    if (row0 >= n_e) return;
    const float* B = (e < En) ? (wd + (size_t)e * In * Hn) : shd;
    const int off_e = g_offsets[e];
    const int colb = nt * BN;

    extern __shared__ float smem[];
    float* As = smem;                  // [2][64][AS_P]
    float* Bs = smem + 2 * BM * AS_P;  // [2][32][BS_P]

    const int tid = threadIdx.x;

    const float* a_src[4];
    float* a_dst[4];
    {
        int c4 = tid & 7;
        #pragma unroll
        for (int l = 0; l < 4; l++) {
            int r = (tid >> 3) + 16 * l;
            int ridx = row0 + r; if (ridx > n_e - 1) ridx = n_e - 1;
            a_src[l] = g_act + (size_t)(off_e + ridx) * In + c4 * 4;
            a_dst[l] = As + r * AS_P + c4 * 4;
        }
    }
    const float* b_src[4];
    float* b_dst[4];
    {
        int c4 = tid & 15;
        #pragma unroll
        for (int l = 0; l < 4; l++) {
            int id = tid + l * 128;
            int r = id >> 4;  // 0..31
            b_src[l] = B + (size_t)r * Hn + colb + c4 * 4;
            b_dst[l] = Bs + r * BS_P + c4 * 4;
        }
    }

    const int w = tid >> 5, lane = tid & 31;
    const int wm = w & 1, wn = w >> 1;
    const int qr = lane >> 2, qc = lane & 3;
    const int abuf_sz = BM * AS_P, bbuf_sz = BK * BS_P;

    float acc[2][4][4];
    #pragma unroll
    for (int m = 0; m < 2; m++)
        #pragma unroll
        for (int n = 0; n < 4; n++)
            #pragma unroll
            for (int j = 0; j < 4; j++) acc[m][n][j] = 0.f;

    #pragma unroll
    for (int l = 0; l < 4; l++) cpa16(a_dst[l], a_src[l]);
    #pragma unroll
    for (int l = 0; l < 4; l++) cpa16(b_dst[l], b_src[l]);
    cpa_commit();

    const int KT = In / BK;  // 16
    for (int kt = 0; kt < KT; kt++) {
        int buf = kt & 1;
        if (kt + 1 < KT) {
            int nb = buf ^ 1;
            int aoff = nb ? abuf_sz : 0;
            int boff = nb ? bbuf_sz : 0;
            size_t ka = (size_t)(kt + 1) * BK;
            #pragma unroll
            for (int l = 0; l < 4; l++)
                cpa16(a_dst[l] + aoff, a_src[l] + ka);
            #pragma unroll
            for (int l = 0; l < 4; l++)
                cpa16(b_dst[l] + boff, b_src[l] + ka * Hn);
            cpa_commit();
            cpa_wait1();
        } else {
            cpa_wait0();
        }
        __syncthreads();

        const float* Ab = As + buf * abuf_sz;
        const float* Bb = Bs + buf * bbuf_sz;
        #pragma unroll
        for (int ks = 0; ks < BK; ks += 8) {
            unsigned a[2][4];
            #pragma unroll
            for (int m = 0; m < 2; m++) {
                int r0 = wm * 32 + m * 16 + qr;
                a[m][0] = f2tf(Ab[r0 * AS_P + ks + qc]);
                a[m][1] = f2tf(Ab[(r0 + 8) * AS_P + ks + qc]);
                a[m][2] = f2tf(Ab[r0 * AS_P + ks + qc + 4]);
                a[m][3] = f2tf(Ab[(r0 + 8) * AS_P + ks + qc + 4]);
            }
            #pragma unroll
            for (int n = 0; n < 4; n++) {
                int c = wn * 32 + n * 8 + qr;
                unsigned b0 = f2tf(Bb[(ks + qc) * BS_P + c]);
                unsigned b1 = f2tf(Bb[(ks + qc + 4) * BS_P + c]);
                #pragma unroll
                for (int m = 0; m < 2; m++)
                    mma_tf32(acc[m][n], a[m][0], a[m][1], a[m][2], a[m][3], b0, b1);
            }
        }
        __syncthreads();
    }

    #pragma unroll
    for (int m = 0; m < 2; m++) {
        #pragma unroll
        for (int n = 0; n < 4; n++) {
            #pragma unroll
            for (int half = 0; half < 2; half++) {
                int r = wm * 32 + m * 16 + qr + half * 8;
                int grow = row0 + r;
                if (grow < n_e) {
                    int c = colb + wn * 32 + n * 8 + qc * 2;
                    float2 o;
                    o.x = acc[m][n][half * 2 + 0];
                    o.y = acc[m][n][half * 2 + 1];
                    *(float2*)(g_down + (size_t)(off_e + grow) * Hn + c) = o;
                }
            }
        }
    }
}

// ---------------- kernel 5: weighted combine ----------------
__global__ void k_combine(float* __restrict__ out) {
    int t = blockIdx.x, tid = threadIdx.x;
    __shared__ int s_slot[9];
    __shared__ float s_w[9];
    if (tid < TOPK) {
        int ee = g_tk_e[t * TOPK + tid];
        s_slot[tid] = g_offsets[ee] + g_tk_pos[t * TOPK + tid];
        s_w[tid] = g_tk_w[t * TOPK + tid];
    } else if (tid == TOPK) {
        s_slot[8] = g_offsets[En] + t;  // shared expert slot
        s_w[8] = 1.f;
    }
    __syncthreads();
    int h = tid * 4;
    float4 acc = make_float4(0.f, 0.f, 0.f, 0.f);
    #pragma unroll
    for (int j = 0; j < 9; j++) {
        float4 v = *(const float4*)(g_down + (size_t)s_slot[j] * Hn + h);
        float wv = s_w[j];
        acc.x += wv * v.x; acc.y += wv * v.y;
        acc.z += wv * v.z; acc.w += wv * v.w;
    }
    *(float4*)(out + (size_t)t * Hn + h) = acc;
}

// ---------------- launch ----------------
extern "C" void kernel_launch(void* const* d_in, const int* in_sizes, int n_in,
                              void* d_out, int out_size) {
    const float* x    = (const float*)d_in[0];
    const float* gw   = (const float*)d_in[1];
    const float* eb   = (const float*)d_in[2];
    const float* wgu  = (const float*)d_in[3];
    const float* wd   = (const float*)d_in[4];
    const float* shgu = (const float*)d_in[5];
    const float* shd  = (const float*)d_in[6];
    float* out = (float*)d_out;

    const int smem1 = (2 * BM * AS_P + 4 * BK * BS_P) * 4;  // 55296 B
    const int smem2 = (2 * BM * AS_P + 2 * BK * BS_P) * 4;  // 36864 B
    cudaFuncSetAttribute(k_gemm1, cudaFuncAttributeMaxDynamicSharedMemorySize, smem1);
    cudaFuncSetAttribute(k_gemm2, cudaFuncAttributeMaxDynamicSharedMemorySize, smem2);

    k_init<<<1, 128>>>();
    k_route<<<Tn, 256>>>(x, gw, eb);
    k_scan<<<1, 1>>>();
    k_gemm1<<<dim3(16 * 8, NV), 128, smem1>>>(x, wgu, shgu);
    k_gemm2<<<dim3(16 * 16, NV), 128, smem2>>>(wd, shd);
    k_combine<<<Tn, 256>>>(out);
}